// round 1
// baseline (speedup 1.0000x reference)
#include <cuda_runtime.h>

#define NPTS   6144
#define ROWS   128          // threads per block == rows per block
#define SPLIT  16           // j-dimension split for occupancy
#define KCHUNK (NPTS / SPLIT)   // 384 j's per block
#define TILE_J 128          // j's per shared-memory tile
#define NOUT   17

// deterministic partial buffer: [SPLIT][NOUT][NPTS]
__device__ float g_partials[SPLIT * NOUT * NPTS];

__global__ __launch_bounds__(ROWS) void rbf_main(
    const float* __restrict__ x,  const float* __restrict__ z,
    const float* __restrict__ t,  const float* __restrict__ c,
    const float* __restrict__ v1, const float* __restrict__ v2,
    const float* __restrict__ v3, const float* __restrict__ v4)
{
    __shared__ float4 tile[TILE_J * 2];   // per j: {cx,cz,ct,v1},{v2,v3,v4,0}

    const int tid = threadIdx.x;
    const int i   = blockIdx.x * ROWS + tid;   // my row
    const int by  = blockIdx.y;                // my j-split

    const float xi = x[i];
    const float zi = z[i];
    const float ti = t[i];

    float acc[NOUT];
#pragma unroll
    for (int k = 0; k < NOUT; k++) acc[k] = 0.0f;

    const int jbase = by * KCHUNK;

    for (int j0 = 0; j0 < KCHUNK; j0 += TILE_J) {
        // cooperative tile load: one j per thread (ROWS == TILE_J)
        {
            const int j = jbase + j0 + tid;
            tile[tid * 2]     = make_float4(c[j * 3 + 0], c[j * 3 + 1],
                                            c[j * 3 + 2], v1[j]);
            tile[tid * 2 + 1] = make_float4(v2[j], v3[j], v4[j], 0.0f);
        }
        __syncthreads();

#pragma unroll 8
        for (int l = 0; l < TILE_J; l++) {
            const float4 a = tile[l * 2];
            const float4 b = tile[l * 2 + 1];

            const float dx = a.x - xi;
            const float dz = a.y - zi;
            const float dtt = a.z - ti;
            const float r2 = fmaf(dx, dx, fmaf(dz, dz, dtt * dtt));
            const float g  = __expf(-0.5f * r2);

            const float wx  = g * dx;
            const float wz  = g * dz;
            const float wt  = g * dtt;
            const float wxx = fmaf(wx, dx, -g);   // G*(dx^2 - 1)
            const float wzz = fmaf(wz, dz, -g);   // G*(dz^2 - 1)

            const float vv1 = a.w, vv2 = b.x, vv3 = b.y, vv4 = b.z;

            acc[0]  = fmaf(wx,  vv3, acc[0]);   // dudx
            acc[1]  = fmaf(wz,  vv3, acc[1]);   // dudz
            acc[2]  = fmaf(wt,  vv3, acc[2]);   // dudt
            acc[3]  = fmaf(wx,  vv4, acc[3]);   // dwdx
            acc[4]  = fmaf(wz,  vv4, acc[4]);   // dwdz
            acc[5]  = fmaf(wt,  vv4, acc[5]);   // dwdt
            acc[6]  = fmaf(wx,  vv2, acc[6]);   // dbdx
            acc[7]  = fmaf(wz,  vv2, acc[7]);   // dbdz
            acc[8]  = fmaf(wt,  vv2, acc[8]);   // dbdt
            acc[9]  = fmaf(wx,  vv1, acc[9]);   // dpdx
            acc[10] = fmaf(wz,  vv1, acc[10]);  // dpdz
            acc[11] = fmaf(wxx, vv3, acc[11]);  // d2ud2x
            acc[12] = fmaf(wzz, vv3, acc[12]);  // d2ud2z
            acc[13] = fmaf(wxx, vv4, acc[13]);  // d2wd2x
            acc[14] = fmaf(wzz, vv4, acc[14]);  // d2wd2z
            acc[15] = fmaf(wxx, vv2, acc[15]);  // d2bd2x
            acc[16] = fmaf(wzz, vv2, acc[16]);  // d2bd2z
        }
        __syncthreads();
    }

#pragma unroll
    for (int k = 0; k < NOUT; k++)
        g_partials[(by * NOUT + k) * NPTS + i] = acc[k];
}

__global__ void rbf_reduce(float* __restrict__ out)
{
    const int idx = blockIdx.x * blockDim.x + threadIdx.x;
    if (idx >= NOUT * NPTS) return;
    float s = 0.0f;
#pragma unroll
    for (int sidx = 0; sidx < SPLIT; sidx++)
        s += g_partials[sidx * (NOUT * NPTS) + idx];
    out[idx] = s;
}

extern "C" void kernel_launch(void* const* d_in, const int* in_sizes, int n_in,
                              void* d_out, int out_size)
{
    const float* x  = (const float*)d_in[0];
    const float* z  = (const float*)d_in[1];
    const float* t  = (const float*)d_in[2];
    const float* c  = (const float*)d_in[3];
    const float* v1 = (const float*)d_in[4];
    const float* v2 = (const float*)d_in[5];
    const float* v3 = (const float*)d_in[6];
    const float* v4 = (const float*)d_in[7];
    float* out = (float*)d_out;

    dim3 grid(NPTS / ROWS, SPLIT);   // (48, 16)
    rbf_main<<<grid, ROWS>>>(x, z, t, c, v1, v2, v3, v4);

    const int total = NOUT * NPTS;
    rbf_reduce<<<(total + 255) / 256, 256>>>(out);
}

// round 2
// speedup vs baseline: 1.1143x; 1.1143x over previous
#include <cuda_runtime.h>

#define NPTS   6144
#define THREADS 128
#define ROWS_PER_BLOCK 256        // 2 rows per thread, packed f32x2
#define SPLIT  24
#define KCHUNK (NPTS / SPLIT)     // 256
#define TILE_J 128
#define NOUT   17

typedef unsigned long long u64;

// deterministic partial buffer: [SPLIT][NOUT][NPTS]  (~10 MB)
__device__ float g_partials[SPLIT * NOUT * NPTS];

// ---- packed f32x2 helpers (sm_100+) ----
__device__ __forceinline__ u64 pk2(float lo, float hi) {
    u64 r; asm("mov.b64 %0, {%1, %2};" : "=l"(r) : "f"(lo), "f"(hi)); return r;
}
__device__ __forceinline__ void upk2(u64 v, float& lo, float& hi) {
    asm("mov.b64 {%0, %1}, %2;" : "=f"(lo), "=f"(hi) : "l"(v));
}
__device__ __forceinline__ u64 fma2(u64 a, u64 b, u64 c) {
    u64 d; asm("fma.rn.f32x2 %0, %1, %2, %3;" : "=l"(d) : "l"(a), "l"(b), "l"(c)); return d;
}
__device__ __forceinline__ u64 mul2(u64 a, u64 b) {
    u64 d; asm("mul.rn.f32x2 %0, %1, %2;" : "=l"(d) : "l"(a), "l"(b)); return d;
}
__device__ __forceinline__ u64 add2(u64 a, u64 b) {
    u64 d; asm("add.rn.f32x2 %0, %1, %2;" : "=l"(d) : "l"(a), "l"(b)); return d;
}
__device__ __forceinline__ u64 neg2(u64 a) {   // flip both sign bits (ALU pipe)
    u64 d; asm("xor.b64 %0, %1, 0x8000000080000000;" : "=l"(d) : "l"(a)); return d;
}
__device__ __forceinline__ float ex2f(float a) {
    float r; asm("ex2.approx.ftz.f32 %0, %1;" : "=f"(r) : "f"(a)); return r;
}

__global__ __launch_bounds__(THREADS) void rbf_main(
    const float* __restrict__ x,  const float* __restrict__ z,
    const float* __restrict__ t,  const float* __restrict__ c,
    const float* __restrict__ v1, const float* __restrict__ v2,
    const float* __restrict__ v3, const float* __restrict__ v4)
{
    // per j: 8 u64 slots, each value pre-duplicated {v,v}
    // [cx2, cz2, ct2, v1_2] [v2_2, v3_2, v4_2, pad]
    __shared__ u64 tile[TILE_J][8];

    const int tid = threadIdx.x;
    const int i0  = blockIdx.x * ROWS_PER_BLOCK + tid;
    const int i1  = i0 + THREADS;
    const int by  = blockIdx.y;

    const u64 nxi = pk2(-x[i0], -x[i1]);
    const u64 nzi = pk2(-z[i0], -z[i1]);
    const u64 nti = pk2(-t[i0], -t[i1]);

    // -0.5 * log2(e): fold exp() scale into one packed mul
    const u64 kc = pk2(-0.72134752044448170f, -0.72134752044448170f);

    u64 acc[NOUT];
#pragma unroll
    for (int k = 0; k < NOUT; k++) acc[k] = 0ULL;   // {0.0f, 0.0f}

    const int jbase = by * KCHUNK;

    for (int j0 = 0; j0 < KCHUNK; j0 += TILE_J) {
        {   // cooperative duplicated-tile load (one j per thread)
            const int j = jbase + j0 + tid;
            const float cx = c[j * 3 + 0];
            const float cz = c[j * 3 + 1];
            const float ct = c[j * 3 + 2];
            const float a1 = v1[j], a2 = v2[j], a3 = v3[j], a4 = v4[j];
            tile[tid][0] = pk2(cx, cx);
            tile[tid][1] = pk2(cz, cz);
            tile[tid][2] = pk2(ct, ct);
            tile[tid][3] = pk2(a1, a1);
            tile[tid][4] = pk2(a2, a2);
            tile[tid][5] = pk2(a3, a3);
            tile[tid][6] = pk2(a4, a4);
        }
        __syncthreads();

#pragma unroll 4
        for (int l = 0; l < TILE_J; l++) {
            const ulonglong2* tp = reinterpret_cast<const ulonglong2*>(tile[l]);
            const ulonglong2 p0 = tp[0];        // LDS.128 broadcast
            const ulonglong2 p1 = tp[1];
            const ulonglong2 p2 = tp[2];
            const u64 cx2 = p0.x, cz2 = p0.y;
            const u64 ct2 = p1.x, v12 = p1.y;
            const u64 v22 = p2.x, v32 = p2.y;
            const u64 v42 = tile[l][6];         // LDS.64 broadcast

            const u64 dx  = add2(cx2, nxi);
            const u64 dz  = add2(cz2, nzi);
            const u64 dtt = add2(ct2, nti);
            const u64 r2  = fma2(dx, dx, fma2(dz, dz, mul2(dtt, dtt)));
            const u64 m   = mul2(r2, kc);

            float mlo, mhi;  upk2(m, mlo, mhi);
            const u64 g  = pk2(ex2f(mlo), ex2f(mhi));
            const u64 ng = neg2(g);

            const u64 wx  = mul2(g, dx);
            const u64 wz  = mul2(g, dz);
            const u64 wt  = mul2(g, dtt);
            const u64 wxx = fma2(wx, dx, ng);   // G*(dx^2 - 1)
            const u64 wzz = fma2(wz, dz, ng);   // G*(dz^2 - 1)

            acc[0]  = fma2(wx,  v32, acc[0]);   // dudx
            acc[1]  = fma2(wz,  v32, acc[1]);   // dudz
            acc[2]  = fma2(wt,  v32, acc[2]);   // dudt
            acc[3]  = fma2(wx,  v42, acc[3]);   // dwdx
            acc[4]  = fma2(wz,  v42, acc[4]);   // dwdz
            acc[5]  = fma2(wt,  v42, acc[5]);   // dwdt
            acc[6]  = fma2(wx,  v22, acc[6]);   // dbdx
            acc[7]  = fma2(wz,  v22, acc[7]);   // dbdz
            acc[8]  = fma2(wt,  v22, acc[8]);   // dbdt
            acc[9]  = fma2(wx,  v12, acc[9]);   // dpdx
            acc[10] = fma2(wz,  v12, acc[10]);  // dpdz
            acc[11] = fma2(wxx, v32, acc[11]);  // d2ud2x
            acc[12] = fma2(wzz, v32, acc[12]);  // d2ud2z
            acc[13] = fma2(wxx, v42, acc[13]);  // d2wd2x
            acc[14] = fma2(wzz, v42, acc[14]);  // d2wd2z
            acc[15] = fma2(wxx, v22, acc[15]);  // d2bd2x
            acc[16] = fma2(wzz, v22, acc[16]);  // d2bd2z
        }
        __syncthreads();
    }

#pragma unroll
    for (int k = 0; k < NOUT; k++) {
        float lo, hi;  upk2(acc[k], lo, hi);
        g_partials[(by * NOUT + k) * NPTS + i0] = lo;
        g_partials[(by * NOUT + k) * NPTS + i1] = hi;
    }
}

// vectorized deterministic reduction: 24 independent LDG.128 per thread
__global__ void rbf_reduce(float4* __restrict__ out)
{
    const int idx = blockIdx.x * blockDim.x + threadIdx.x;
    const int nvec = (NOUT * NPTS) / 4;            // 26112
    if (idx >= nvec) return;
    const float4* p = reinterpret_cast<const float4*>(g_partials);
    float4 s = make_float4(0.f, 0.f, 0.f, 0.f);
#pragma unroll
    for (int sidx = 0; sidx < SPLIT; sidx++) {
        const float4 v = p[sidx * nvec + idx];
        s.x += v.x; s.y += v.y; s.z += v.z; s.w += v.w;
    }
    out[idx] = s;
}

extern "C" void kernel_launch(void* const* d_in, const int* in_sizes, int n_in,
                              void* d_out, int out_size)
{
    const float* x  = (const float*)d_in[0];
    const float* z  = (const float*)d_in[1];
    const float* t  = (const float*)d_in[2];
    const float* c  = (const float*)d_in[3];
    const float* v1 = (const float*)d_in[4];
    const float* v2 = (const float*)d_in[5];
    const float* v3 = (const float*)d_in[6];
    const float* v4 = (const float*)d_in[7];

    dim3 grid(NPTS / ROWS_PER_BLOCK, SPLIT);   // (24, 24)
    rbf_main<<<grid, THREADS>>>(x, z, t, c, v1, v2, v3, v4);

    const int nvec = (NOUT * NPTS) / 4;        // 26112
    rbf_reduce<<<(nvec + 255) / 256, 256>>>((float4*)d_out);
}

// round 4
// speedup vs baseline: 1.3691x; 1.2287x over previous
#include <cuda_runtime.h>
#include <cstdint>

typedef unsigned long long u64;
typedef unsigned int u32;

#define NPTS    6144
#define JSPLIT  6
#define IBLK    (NPTS / 256)          // 24 i-blocks (256 rows each)
#define KSTEPS  (NPTS / 16)           // 384 total k-steps (16 j each)
#define KSPB    (KSTEPS / JSPLIT)     // 64 k-steps per block
#define KS_STAGE 8                    // k-steps per smem stage
#define NSTAGE  (KSPB / KS_STAGE)     // 8
#define NMOM    24                    // moment columns (21 used, padded)

// ---------------- device scratch ----------------
// per-j A-side data: {cx*L2E dup, cz*L2E dup, ct*L2E dup, -0.5|c|^2*L2E dup} (32B/j)
__device__ u64 g_cpk[NPTS * 4];
// B fragments: [ks][h(hi/lo)][n(0..2)][lane] u64 = {b0, b1} bf16x2 pair
__device__ u64 g_Bf[KSTEPS * 2 * 3 * 32];
// moment partials: [JSPLIT][NPTS][NMOM]
__device__ float g_part[JSPLIT * NPTS * NMOM];

// ---------------- helpers ----------------
__device__ __forceinline__ u32 smem_u32(const void* p) {
    u32 a; asm("{ .reg .u64 t; cvta.to.shared.u64 t, %1; cvt.u32.u64 %0, t; }" : "=r"(a) : "l"(p));
    return a;
}
__device__ __forceinline__ u64 pk2(float lo, float hi) {
    u64 r; asm("mov.b64 %0, {%1, %2};" : "=l"(r) : "f"(lo), "f"(hi)); return r;
}
__device__ __forceinline__ void upk2(u64 v, float& lo, float& hi) {
    asm("mov.b64 {%0, %1}, %2;" : "=f"(lo), "=f"(hi) : "l"(v));
}
__device__ __forceinline__ u64 fma2(u64 a, u64 b, u64 c) {
    u64 d; asm("fma.rn.f32x2 %0, %1, %2, %3;" : "=l"(d) : "l"(a), "l"(b), "l"(c)); return d;
}
__device__ __forceinline__ float ex2f(float a) {
    float r; asm("ex2.approx.ftz.f32 %0, %1;" : "=f"(r) : "f"(a)); return r;
}
// pack two f32 -> bf16x2 (lo in low 16 bits)
__device__ __forceinline__ u32 bfpk(float lo, float hi) {
    u32 d; asm("cvt.rn.bf16x2.f32 %0, %1, %2;" : "=r"(d) : "f"(hi), "f"(lo)); return d;
}
__device__ __forceinline__ u32 prmt0(u32 a, u32 ctl) {
    u32 d; asm("prmt.b32 %0, %1, 0, %2;" : "=r"(d) : "r"(a), "r"(ctl)); return d;
}
__device__ __forceinline__ void cpa16(u32 saddr, const void* g) {
    asm volatile("cp.async.cg.shared.global [%0], [%1], 16;" :: "r"(saddr), "l"(g));
}
__device__ __forceinline__ void cpa_commit() { asm volatile("cp.async.commit_group;" ::: "memory"); }
template <int N> __device__ __forceinline__ void cpa_wait() {
    asm volatile("cp.async.wait_group %0;" :: "n"(N) : "memory");
}
__device__ __forceinline__ void mma_bf16(float* c, const u32* a, const u32* b) {
    asm volatile(
        "mma.sync.aligned.m16n8k16.row.col.f32.bf16.bf16.f32 "
        "{%0,%1,%2,%3}, {%4,%5,%6,%7}, {%8,%9}, {%0,%1,%2,%3};"
        : "+f"(c[0]), "+f"(c[1]), "+f"(c[2]), "+f"(c[3])
        : "r"(a[0]), "r"(a[1]), "r"(a[2]), "r"(a[3]), "r"(b[0]), "r"(b[1]));
}
// split two f32 (g0->k-even, g1->k-odd) into bf16 hi reg + bf16 lo reg
__device__ __forceinline__ void bfsplit(float g0, float g1, u32& hi, u32& lo) {
    hi = bfpk(g0, g1);
    float h0 = __uint_as_float(prmt0(hi, 0x1044));   // {b1,b0,0,0}
    float h1 = __uint_as_float(prmt0(hi, 0x3244));   // {b3,b2,0,0}
    lo = bfpk(g0 - h0, g1 - h1);
}

// ---------------- prep: per-j A-side constants ----------------
__global__ void prep_c(const float* __restrict__ c)
{
    const int j = blockIdx.x * blockDim.x + threadIdx.x;
    if (j >= NPTS) return;
    const float L2E = 1.4426950408889634f;
    const float cx = c[3 * j], cz = c[3 * j + 1], ct = c[3 * j + 2];
    const float kc = -0.5f * (cx * cx + cz * cz + ct * ct) * L2E;
    g_cpk[j * 4 + 0] = pk2(cx * L2E, cx * L2E);
    g_cpk[j * 4 + 1] = pk2(cz * L2E, cz * L2E);
    g_cpk[j * 4 + 2] = pk2(ct * L2E, ct * L2E);
    g_cpk[j * 4 + 3] = pk2(kc, kc);
}

// ---------------- prep: B fragments (bf16 hi/lo, mma col-major layout) ----------------
__global__ void prep_B(const float* __restrict__ c,
                       const float* __restrict__ v1, const float* __restrict__ v2,
                       const float* __restrict__ v3, const float* __restrict__ v4)
{
    const int idx = blockIdx.x * blockDim.x + threadIdx.x;
    if (idx >= KSTEPS * 96) return;
    const int lane = idx & 31;
    const int n    = (idx >> 5) % 3;
    const int ks   = idx / 96;
    const int cc   = lane & 3, g = lane >> 2;
    const int m    = n * 8 + g;

    float u[4];
#pragma unroll
    for (int q = 0; q < 4; q++) {
        const int j = ks * 16 + 2 * cc + (q & 1) + ((q >> 1) << 3);
        float val = 0.0f;
        if (m < 21) {
            const float cx = c[3 * j], cz = c[3 * j + 1], ct = c[3 * j + 2];
            float vv, base;
            int r6;
            if (m < 3) { vv = v1[j]; r6 = m; }
            else {
                const int g2 = (m - 3) / 6;
                vv = (g2 == 0) ? v2[j] : (g2 == 1) ? v3[j] : v4[j];
                r6 = (m - 3) % 6;
            }
            base = (r6 == 0) ? 1.0f : (r6 == 1) ? cx : (r6 == 2) ? cz :
                   (r6 == 3) ? ct   : (r6 == 4) ? cx * cx : cz * cz;
            val = base * vv;
        }
        u[q] = val;
    }
    u32 b0h, b0l, b1h, b1l;
    bfsplit(u[0], u[1], b0h, b0l);   // k rows {2c, 2c+1}
    bfsplit(u[2], u[3], b1h, b1l);   // k rows {2c+8, 2c+9}
    g_Bf[(ks * 2 + 0) * 96 + n * 32 + lane] = ((u64)b1h << 32) | b0h;
    g_Bf[(ks * 2 + 1) * 96 + n * 32 + lane] = ((u64)b1l << 32) | b0l;
}

// ---------------- main: fused exp + bf16-split moment GEMM ----------------
__global__ __launch_bounds__(256, 1) void rbf_mma(
    const float* __restrict__ x, const float* __restrict__ z, const float* __restrict__ t)
{
    __shared__ __align__(16) char sB[2][KS_STAGE * 1536];   // 2 x 12KB
    __shared__ __align__(16) char sC[2][KS_STAGE * 512];    // 2 x 4KB

    const int tid  = threadIdx.x;
    const int w    = tid >> 5, lane = tid & 31;
    const int r    = lane >> 2, cc = lane & 3;
    const int ib   = blockIdx.x, js = blockIdx.y;
    const int i0   = ib * 256 + w * 32;

    // packed row coordinates: rowpair0 = (r, r+8), rowpair1 = (r+16, r+24)
    const u64 xp0 = pk2(x[i0 + r], x[i0 + r + 8]);
    const u64 xp1 = pk2(x[i0 + r + 16], x[i0 + r + 24]);
    const u64 zp0 = pk2(z[i0 + r], z[i0 + r + 8]);
    const u64 zp1 = pk2(z[i0 + r + 16], z[i0 + r + 24]);
    const u64 tp0 = pk2(t[i0 + r], t[i0 + r + 8]);
    const u64 tp1 = pk2(t[i0 + r + 16], t[i0 + r + 24]);

    float acc[2][3][4];
#pragma unroll
    for (int a = 0; a < 2; a++)
#pragma unroll
        for (int b = 0; b < 3; b++)
#pragma unroll
            for (int q = 0; q < 4; q++) acc[a][b][q] = 0.0f;

    const int ks0 = js * KSPB;
    const char* gB = (const char*)g_Bf + (u64)ks0 * 1536;
    const char* gC = (const char*)g_cpk + (u64)ks0 * 512;

    // prologue prefetch stage 0
    {
        u32 dB = smem_u32(&sB[0][0]);
#pragma unroll
        for (int q = 0; q < 3; q++) cpa16(dB + tid * 16 + q * 4096, gB + tid * 16 + q * 4096);
        cpa16(smem_u32(&sC[0][0]) + tid * 16, gC + tid * 16);
        cpa_commit();
    }

    for (int st = 0; st < NSTAGE; st++) {
        const int buf = st & 1;
        if (st + 1 < NSTAGE) {
            const int nb = buf ^ 1;
            u32 dB = smem_u32(&sB[nb][0]);
            const char* sBg = gB + (u64)(st + 1) * (KS_STAGE * 1536);
#pragma unroll
            for (int q = 0; q < 3; q++) cpa16(dB + tid * 16 + q * 4096, sBg + tid * 16 + q * 4096);
            cpa16(smem_u32(&sC[nb][0]) + tid * 16, gC + (u64)(st + 1) * (KS_STAGE * 512) + tid * 16);
            cpa_commit();
            cpa_wait<1>();
        } else {
            cpa_wait<0>();
        }
        __syncthreads();

#pragma unroll 1
        for (int k = 0; k < KS_STAGE; k++) {
            // ---- A side: 16 G' values ----
            float G0[4], G1[4], G2[4], G3[4];
#pragma unroll
            for (int jj = 0; jj < 4; jj++) {
                const int jloc = 2 * cc + (jj & 1) + ((jj >> 1) << 3);
                const char* cp = &sC[buf][k * 512 + jloc * 32];
                const ulonglong2 q0 = *(const ulonglong2*)cp;
                const ulonglong2 q1 = *(const ulonglong2*)(cp + 16);
                u64 d0 = fma2(q1.x, tp0, q1.y);
                d0 = fma2(q0.y, zp0, d0);
                d0 = fma2(q0.x, xp0, d0);
                u64 d1 = fma2(q1.x, tp1, q1.y);
                d1 = fma2(q0.y, zp1, d1);
                d1 = fma2(q0.x, xp1, d1);
                float f0, f1, f2, f3; upk2(d0, f0, f1); upk2(d1, f2, f3);
                G0[jj] = ex2f(f0); G1[jj] = ex2f(f1);
                G2[jj] = ex2f(f2); G3[jj] = ex2f(f3);
            }
            u32 ah[2][4], al[2][4];
            bfsplit(G0[0], G0[1], ah[0][0], al[0][0]);
            bfsplit(G1[0], G1[1], ah[0][1], al[0][1]);
            bfsplit(G0[2], G0[3], ah[0][2], al[0][2]);
            bfsplit(G1[2], G1[3], ah[0][3], al[0][3]);
            bfsplit(G2[0], G2[1], ah[1][0], al[1][0]);
            bfsplit(G3[0], G3[1], ah[1][1], al[1][1]);
            bfsplit(G2[2], G2[3], ah[1][2], al[1][2]);
            bfsplit(G3[2], G3[3], ah[1][3], al[1][3]);

            // ---- B frags ----
            u32 bh[3][2], bl[3][2];
            const char* bp = &sB[buf][k * 1536 + lane * 8];
#pragma unroll
            for (int n = 0; n < 3; n++) {
                const uint2 vh = *(const uint2*)(bp + n * 256);
                const uint2 vl = *(const uint2*)(bp + 768 + n * 256);
                bh[n][0] = vh.x; bh[n][1] = vh.y;
                bl[n][0] = vl.x; bl[n][1] = vl.y;
            }

            // ---- 18 MMAs: hi*hi + lo*hi + hi*lo ----
#pragma unroll
            for (int mt = 0; mt < 2; mt++)
#pragma unroll
                for (int n = 0; n < 3; n++) {
                    mma_bf16(acc[mt][n], ah[mt], bh[n]);
                    mma_bf16(acc[mt][n], al[mt], bh[n]);
                    mma_bf16(acc[mt][n], ah[mt], bl[n]);
                }
        }
        __syncthreads();
    }

    // ---- write moment partials ----
#pragma unroll
    for (int mt = 0; mt < 2; mt++)
#pragma unroll
        for (int n = 0; n < 3; n++) {
            const int row = i0 + mt * 16 + r;
            const int col = n * 8 + 2 * cc;
            float2* d0 = (float2*)&g_part[((u64)js * NPTS + row) * NMOM + col];
            float2* d1 = (float2*)&g_part[((u64)js * NPTS + row + 8) * NMOM + col];
            *d0 = make_float2(acc[mt][n][0], acc[mt][n][1]);
            *d1 = make_float2(acc[mt][n][2], acc[mt][n][3]);
        }
}

// ---------------- epilogue: reduce splits + apply e^{-.5|p|^2} + combos ----------------
__global__ void rbf_epi(const float* __restrict__ x, const float* __restrict__ z,
                        const float* __restrict__ t, float* __restrict__ out)
{
    const int i = blockIdx.x * blockDim.x + threadIdx.x;
    if (i >= NPTS) return;
    float S[NMOM];
#pragma unroll
    for (int m = 0; m < NMOM; m++) S[m] = 0.0f;
#pragma unroll
    for (int js = 0; js < JSPLIT; js++) {
        const float4* p = (const float4*)&g_part[((u64)js * NPTS + i) * NMOM];
#pragma unroll
        for (int q = 0; q < 6; q++) {
            const float4 v = p[q];
            S[q * 4 + 0] += v.x; S[q * 4 + 1] += v.y;
            S[q * 4 + 2] += v.z; S[q * 4 + 3] += v.w;
        }
    }
    const float xi = x[i], zi = z[i], ti = t[i];
    const float ep = __expf(-0.5f * (xi * xi + zi * zi + ti * ti));
#pragma unroll
    for (int m = 0; m < 21; m++) S[m] *= ep;
    const float xx = xi * xi - 1.0f, zz = zi * zi - 1.0f;

    out[0  * NPTS + i] = S[10] - xi * S[9];
    out[1  * NPTS + i] = S[11] - zi * S[9];
    out[2  * NPTS + i] = S[12] - ti * S[9];
    out[3  * NPTS + i] = S[16] - xi * S[15];
    out[4  * NPTS + i] = S[17] - zi * S[15];
    out[5  * NPTS + i] = S[18] - ti * S[15];
    out[6  * NPTS + i] = S[4]  - xi * S[3];
    out[7  * NPTS + i] = S[5]  - zi * S[3];
    out[8  * NPTS + i] = S[6]  - ti * S[3];
    out[9  * NPTS + i] = S[1]  - xi * S[0];
    out[10 * NPTS + i] = S[2]  - zi * S[0];
    out[11 * NPTS + i] = S[13] - 2.0f * xi * S[10] + xx * S[9];
    out[12 * NPTS + i] = S[14] - 2.0f * zi * S[11] + zz * S[9];
    out[13 * NPTS + i] = S[19] - 2.0f * xi * S[16] + xx * S[15];
    out[14 * NPTS + i] = S[20] - 2.0f * zi * S[17] + zz * S[15];
    out[15 * NPTS + i] = S[7]  - 2.0f * xi * S[4]  + xx * S[3];
    out[16 * NPTS + i] = S[8]  - 2.0f * zi * S[5]  + zz * S[3];
}

extern "C" void kernel_launch(void* const* d_in, const int* in_sizes, int n_in,
                              void* d_out, int out_size)
{
    const float* x  = (const float*)d_in[0];
    const float* z  = (const float*)d_in[1];
    const float* t  = (const float*)d_in[2];
    const float* c  = (const float*)d_in[3];
    const float* v1 = (const float*)d_in[4];
    const float* v2 = (const float*)d_in[5];
    const float* v3 = (const float*)d_in[6];
    const float* v4 = (const float*)d_in[7];

    prep_c<<<NPTS / 256, 256>>>(c);
    prep_B<<<(KSTEPS * 96) / 256, 256>>>(c, v1, v2, v3, v4);

    dim3 grid(IBLK, JSPLIT);                 // (24, 6) = 144 blocks
    rbf_mma<<<grid, 256>>>(x, z, t);

    rbf_epi<<<NPTS / 256, 256>>>(x, z, t, (float*)d_out);
}

// round 5
// speedup vs baseline: 1.6760x; 1.2241x over previous
#include <cuda_runtime.h>
#include <cuda_fp16.h>
#include <cstdint>

typedef unsigned long long u64;
typedef unsigned int u32;

#define NPTS    6144
#define JSPLIT  12
#define IBLK    (NPTS / 256)          // 24 i-blocks (256 rows each)
#define KSTEPS  (NPTS / 16)           // 384 total k-steps (16 j each)
#define KSPB    (KSTEPS / JSPLIT)     // 32 k-steps per block
#define KS_STAGE 8
#define NSTAGE  (KSPB / KS_STAGE)     // 4
#define NMOM    24                    // moment columns (21 used)

// ---------------- device scratch ----------------
// per-j: {cx*L2E dup, cz*L2E dup, ct*L2E dup, -0.5|c|^2*L2E dup}
__device__ u64 g_cpk[NPTS * 4];
// B fragments: [ks][term(hi/lo)][n(0..2)][lane] u64 = {b0, b1} f16x2 regs
__device__ u64 g_Bf[KSTEPS * 2 * 3 * 32];
// moment partials: [JSPLIT][NPTS][NMOM]
__device__ float g_part[JSPLIT * NPTS * NMOM];

// ---------------- helpers ----------------
__device__ __forceinline__ u32 smem_u32(const void* p) {
    u32 a; asm("{ .reg .u64 t; cvta.to.shared.u64 t, %1; cvt.u32.u64 %0, t; }" : "=r"(a) : "l"(p));
    return a;
}
__device__ __forceinline__ u64 pk2(float lo, float hi) {
    u64 r; asm("mov.b64 %0, {%1, %2};" : "=l"(r) : "f"(lo), "f"(hi)); return r;
}
__device__ __forceinline__ void upk2(u64 v, float& lo, float& hi) {
    asm("mov.b64 {%0, %1}, %2;" : "=f"(lo), "=f"(hi) : "l"(v));
}
__device__ __forceinline__ u64 fma2(u64 a, u64 b, u64 c) {
    u64 d; asm("fma.rn.f32x2 %0, %1, %2, %3;" : "=l"(d) : "l"(a), "l"(b), "l"(c)); return d;
}
__device__ __forceinline__ float ex2f(float a) {
    float r; asm("ex2.approx.ftz.f32 %0, %1;" : "=f"(r) : "f"(a)); return r;
}
// pack two f32 -> f16x2 (lo arg in low 16 bits)
__device__ __forceinline__ u32 f16pk(float lo, float hi) {
    u32 d; asm("cvt.rn.f16x2.f32 %0, %1, %2;" : "=r"(d) : "f"(hi), "f"(lo)); return d;
}
__device__ __forceinline__ void cpa16(u32 saddr, const void* g) {
    asm volatile("cp.async.cg.shared.global [%0], [%1], 16;" :: "r"(saddr), "l"(g));
}
__device__ __forceinline__ void cpa_commit() { asm volatile("cp.async.commit_group;" ::: "memory"); }
template <int N> __device__ __forceinline__ void cpa_wait() {
    asm volatile("cp.async.wait_group %0;" :: "n"(N) : "memory");
}
__device__ __forceinline__ void mma_f16(float* c, const u32* a, const u32* b) {
    asm volatile(
        "mma.sync.aligned.m16n8k16.row.col.f32.f16.f16.f32 "
        "{%0,%1,%2,%3}, {%4,%5,%6,%7}, {%8,%9}, {%0,%1,%2,%3};"
        : "+f"(c[0]), "+f"(c[1]), "+f"(c[2]), "+f"(c[3])
        : "r"(a[0]), "r"(a[1]), "r"(a[2]), "r"(a[3]), "r"(b[0]), "r"(b[1]));
}

// ---------------- merged prep: A-side constants + B fragments ----------------
__global__ void prep_all(const float* __restrict__ c,
                         const float* __restrict__ v1, const float* __restrict__ v2,
                         const float* __restrict__ v3, const float* __restrict__ v4)
{
    const int idx = blockIdx.x * blockDim.x + threadIdx.x;

    // part 1: per-j A-side constants
    if (idx < NPTS) {
        const int j = idx;
        const float L2E = 1.4426950408889634f;
        const float cx = c[3 * j], cz = c[3 * j + 1], ct = c[3 * j + 2];
        const float kc = -0.5f * (cx * cx + cz * cz + ct * ct) * L2E;
        g_cpk[j * 4 + 0] = pk2(cx * L2E, cx * L2E);
        g_cpk[j * 4 + 1] = pk2(cz * L2E, cz * L2E);
        g_cpk[j * 4 + 2] = pk2(ct * L2E, ct * L2E);
        g_cpk[j * 4 + 3] = pk2(kc, kc);
    }

    // part 2: B fragments (fp16 hi/lo, mma col-major fragment layout)
    if (idx < KSTEPS * 96) {
        const int lane = idx & 31;
        const int n    = (idx >> 5) % 3;
        const int ks   = idx / 96;
        const int cc   = lane & 3, g = lane >> 2;
        const int m    = n * 8 + g;

        float u[4];
#pragma unroll
        for (int q = 0; q < 4; q++) {
            const int j = ks * 16 + 2 * cc + (q & 1) + ((q >> 1) << 3);
            float val = 0.0f;
            if (m < 21) {
                const float cx = c[3 * j], cz = c[3 * j + 1], ct = c[3 * j + 2];
                float vv, base;
                int r6;
                if (m < 3) { vv = v1[j]; r6 = m; }
                else {
                    const int g2 = (m - 3) / 6;
                    vv = (g2 == 0) ? v2[j] : (g2 == 1) ? v3[j] : v4[j];
                    r6 = (m - 3) % 6;
                }
                base = (r6 == 0) ? 1.0f : (r6 == 1) ? cx : (r6 == 2) ? cz :
                       (r6 == 3) ? ct   : (r6 == 4) ? cx * cx : cz * cz;
                val = base * vv;
            }
            u[q] = val;
        }
        // fp16 split: hi = rn(u); lo = rn(u - hi)
        const u32 b0h = f16pk(u[0], u[1]);
        const u32 b1h = f16pk(u[2], u[3]);
        const float h00 = __half2float(__ushort_as_half((unsigned short)(b0h & 0xFFFFu)));
        const float h01 = __half2float(__ushort_as_half((unsigned short)(b0h >> 16)));
        const float h10 = __half2float(__ushort_as_half((unsigned short)(b1h & 0xFFFFu)));
        const float h11 = __half2float(__ushort_as_half((unsigned short)(b1h >> 16)));
        const u32 b0l = f16pk(u[0] - h00, u[1] - h01);
        const u32 b1l = f16pk(u[2] - h10, u[3] - h11);
        g_Bf[(ks * 2 + 0) * 96 + n * 32 + lane] = ((u64)b1h << 32) | b0h;
        g_Bf[(ks * 2 + 1) * 96 + n * 32 + lane] = ((u64)b1l << 32) | b0l;
    }
}

// ---------------- main: fused exp + fp16 2-term moment GEMM ----------------
__global__ __launch_bounds__(256, 2) void rbf_mma(
    const float* __restrict__ x, const float* __restrict__ z, const float* __restrict__ t)
{
    __shared__ __align__(16) char sB[2][KS_STAGE * 1536];   // 2 x 12KB
    __shared__ __align__(16) char sC[2][KS_STAGE * 512];    // 2 x 4KB

    const int tid  = threadIdx.x;
    const int w    = tid >> 5, lane = tid & 31;
    const int r    = lane >> 2, cc = lane & 3;
    const int ib   = blockIdx.x, js = blockIdx.y;
    const int i0   = ib * 256 + w * 32;

    const u64 xp0 = pk2(x[i0 + r], x[i0 + r + 8]);
    const u64 xp1 = pk2(x[i0 + r + 16], x[i0 + r + 24]);
    const u64 zp0 = pk2(z[i0 + r], z[i0 + r + 8]);
    const u64 zp1 = pk2(z[i0 + r + 16], z[i0 + r + 24]);
    const u64 tp0 = pk2(t[i0 + r], t[i0 + r + 8]);
    const u64 tp1 = pk2(t[i0 + r + 16], t[i0 + r + 24]);

    float acc[2][3][4];
#pragma unroll
    for (int a = 0; a < 2; a++)
#pragma unroll
        for (int b = 0; b < 3; b++)
#pragma unroll
            for (int q = 0; q < 4; q++) acc[a][b][q] = 0.0f;

    const int ks0 = js * KSPB;
    const char* gB = (const char*)g_Bf + (u64)ks0 * 1536;
    const char* gC = (const char*)g_cpk + (u64)ks0 * 512;

    // prologue prefetch stage 0
    {
        u32 dB = smem_u32(&sB[0][0]);
#pragma unroll
        for (int q = 0; q < 3; q++) cpa16(dB + tid * 16 + q * 4096, gB + tid * 16 + q * 4096);
        cpa16(smem_u32(&sC[0][0]) + tid * 16, gC + tid * 16);
        cpa_commit();
    }

    for (int st = 0; st < NSTAGE; st++) {
        const int buf = st & 1;
        if (st + 1 < NSTAGE) {
            const int nb = buf ^ 1;
            u32 dB = smem_u32(&sB[nb][0]);
            const char* sBg = gB + (u64)(st + 1) * (KS_STAGE * 1536);
#pragma unroll
            for (int q = 0; q < 3; q++) cpa16(dB + tid * 16 + q * 4096, sBg + tid * 16 + q * 4096);
            cpa16(smem_u32(&sC[nb][0]) + tid * 16, gC + (u64)(st + 1) * (KS_STAGE * 512) + tid * 16);
            cpa_commit();
            cpa_wait<1>();
        } else {
            cpa_wait<0>();
        }
        __syncthreads();

#pragma unroll 1
        for (int k = 0; k < KS_STAGE; k++) {
            // ---- A side: 16 G' values, fp16 single precision ----
            float G0[4], G1[4], G2[4], G3[4];
#pragma unroll
            for (int jj = 0; jj < 4; jj++) {
                const int jloc = 2 * cc + (jj & 1) + ((jj >> 1) << 3);
                const char* cp = &sC[buf][k * 512 + jloc * 32];
                const ulonglong2 q0 = *(const ulonglong2*)cp;
                const ulonglong2 q1 = *(const ulonglong2*)(cp + 16);
                u64 d0 = fma2(q1.x, tp0, q1.y);
                d0 = fma2(q0.y, zp0, d0);
                d0 = fma2(q0.x, xp0, d0);
                u64 d1 = fma2(q1.x, tp1, q1.y);
                d1 = fma2(q0.y, zp1, d1);
                d1 = fma2(q0.x, xp1, d1);
                float f0, f1, f2, f3; upk2(d0, f0, f1); upk2(d1, f2, f3);
                G0[jj] = ex2f(f0); G1[jj] = ex2f(f1);
                G2[jj] = ex2f(f2); G3[jj] = ex2f(f3);
            }
            u32 ah[2][4];
            ah[0][0] = f16pk(G0[0], G0[1]);
            ah[0][1] = f16pk(G1[0], G1[1]);
            ah[0][2] = f16pk(G0[2], G0[3]);
            ah[0][3] = f16pk(G1[2], G1[3]);
            ah[1][0] = f16pk(G2[0], G2[1]);
            ah[1][1] = f16pk(G3[0], G3[1]);
            ah[1][2] = f16pk(G2[2], G2[3]);
            ah[1][3] = f16pk(G3[2], G3[3]);

            // ---- B frags (hi + lo) ----
            u32 bh[3][2], bl[3][2];
            const char* bp = &sB[buf][k * 1536 + lane * 8];
#pragma unroll
            for (int n = 0; n < 3; n++) {
                const uint2 vh = *(const uint2*)(bp + n * 256);
                const uint2 vl = *(const uint2*)(bp + 768 + n * 256);
                bh[n][0] = vh.x; bh[n][1] = vh.y;
                bl[n][0] = vl.x; bl[n][1] = vl.y;
            }

            // ---- 12 MMAs: a*bh + a*bl ----
#pragma unroll
            for (int mt = 0; mt < 2; mt++)
#pragma unroll
                for (int n = 0; n < 3; n++) {
                    mma_f16(acc[mt][n], ah[mt], bh[n]);
                    mma_f16(acc[mt][n], ah[mt], bl[n]);
                }
        }
        __syncthreads();
    }

    // ---- write moment partials ----
#pragma unroll
    for (int mt = 0; mt < 2; mt++)
#pragma unroll
        for (int n = 0; n < 3; n++) {
            const int row = i0 + mt * 16 + r;
            const int col = n * 8 + 2 * cc;
            float2* d0 = (float2*)&g_part[((u64)js * NPTS + row) * NMOM + col];
            float2* d1 = (float2*)&g_part[((u64)js * NPTS + row + 8) * NMOM + col];
            *d0 = make_float2(acc[mt][n][0], acc[mt][n][1]);
            *d1 = make_float2(acc[mt][n][2], acc[mt][n][3]);
        }
}

// ---------------- epilogue: reduce splits + apply e^{-.5|p|^2} + combos ----------------
__global__ void rbf_epi(const float* __restrict__ x, const float* __restrict__ z,
                        const float* __restrict__ t, float* __restrict__ out)
{
    const int i = blockIdx.x * blockDim.x + threadIdx.x;
    if (i >= NPTS) return;
    float S[NMOM];
#pragma unroll
    for (int m = 0; m < NMOM; m++) S[m] = 0.0f;
#pragma unroll
    for (int js = 0; js < JSPLIT; js++) {
        const float4* p = (const float4*)&g_part[((u64)js * NPTS + i) * NMOM];
#pragma unroll
        for (int q = 0; q < 6; q++) {
            const float4 v = p[q];
            S[q * 4 + 0] += v.x; S[q * 4 + 1] += v.y;
            S[q * 4 + 2] += v.z; S[q * 4 + 3] += v.w;
        }
    }
    const float xi = x[i], zi = z[i], ti = t[i];
    const float ep = __expf(-0.5f * (xi * xi + zi * zi + ti * ti));
#pragma unroll
    for (int m = 0; m < 21; m++) S[m] *= ep;
    const float xx = xi * xi - 1.0f, zz = zi * zi - 1.0f;

    out[0  * NPTS + i] = S[10] - xi * S[9];
    out[1  * NPTS + i] = S[11] - zi * S[9];
    out[2  * NPTS + i] = S[12] - ti * S[9];
    out[3  * NPTS + i] = S[16] - xi * S[15];
    out[4  * NPTS + i] = S[17] - zi * S[15];
    out[5  * NPTS + i] = S[18] - ti * S[15];
    out[6  * NPTS + i] = S[4]  - xi * S[3];
    out[7  * NPTS + i] = S[5]  - zi * S[3];
    out[8  * NPTS + i] = S[6]  - ti * S[3];
    out[9  * NPTS + i] = S[1]  - xi * S[0];
    out[10 * NPTS + i] = S[2]  - zi * S[0];
    out[11 * NPTS + i] = S[13] - 2.0f * xi * S[10] + xx * S[9];
    out[12 * NPTS + i] = S[14] - 2.0f * zi * S[11] + zz * S[9];
    out[13 * NPTS + i] = S[19] - 2.0f * xi * S[16] + xx * S[15];
    out[14 * NPTS + i] = S[20] - 2.0f * zi * S[17] + zz * S[15];
    out[15 * NPTS + i] = S[7]  - 2.0f * xi * S[4]  + xx * S[3];
    out[16 * NPTS + i] = S[8]  - 2.0f * zi * S[5]  + zz * S[3];
}

extern "C" void kernel_launch(void* const* d_in, const int* in_sizes, int n_in,
                              void* d_out, int out_size)
{
    const float* x  = (const float*)d_in[0];
    const float* z  = (const float*)d_in[1];
    const float* t  = (const float*)d_in[2];
    const float* c  = (const float*)d_in[3];
    const float* v1 = (const float*)d_in[4];
    const float* v2 = (const float*)d_in[5];
    const float* v3 = (const float*)d_in[6];
    const float* v4 = (const float*)d_in[7];

    prep_all<<<(KSTEPS * 96) / 256, 256>>>(c, v1, v2, v3, v4);

    dim3 grid(IBLK, JSPLIT);                 // (24, 12) = 288 blocks
    rbf_mma<<<grid, 256>>>(x, z, t);

    rbf_epi<<<NPTS / 32, 32>>>(x, z, t, (float*)d_out);   // 192 blocks, full-chip
}